// round 5
// baseline (speedup 1.0000x reference)
#include <cuda_runtime.h>
#include <cstdint>
#include <cstddef>

// Problem constants (B=8, S=24, N=4096, K=9, C1=32, C2=16)
#define BS_TOT 192
#define SDIM   24
#define NPTS   4096
#define KNB    9
#define C1V    32
#define C2V    16
#define JTOT   36864   // KNB * NPTS
#define BN_EPS 1e-5f

// ---------------- device scratch (static globals: allocation-free) ----------
__device__ __align__(16) unsigned short d_P[JTOT];  // gather byte-offsets (*16)
__device__ float g_sum[SDIM * C2V];
__device__ float g_sumsq[SDIM * C2V];
__device__ float g_A[SDIM * C2V];
__device__ float g_B[SDIM * C2V];
__device__ float g_T[(size_t)BS_TOT * JTOT];          // transposed input (27 MB)
// h in 4-channel-interleaved layout: g_h4[(bs*8 + qb)*NPTS + p]
__device__ float4 g_h4[(size_t)BS_TOT * 8 * NPTS];    // 96 MB
__device__ float  g_y2[(size_t)BS_TOT * C2V * NPTS];  // stage-2 out (48 MB)

// ---------------- packed f32x2 helpers (sm_103a FFMA2 path) ----------------
__device__ __forceinline__ unsigned long long pack2(float x, float y) {
    unsigned long long r;
    asm("mov.b64 %0, {%1, %2};" : "=l"(r)
        : "r"(__float_as_uint(x)), "r"(__float_as_uint(y)));
    return r;
}
__device__ __forceinline__ float2 unpack2(unsigned long long v) {
    unsigned int a, b;
    asm("mov.b64 {%0, %1}, %2;" : "=r"(a), "=r"(b) : "l"(v));
    return make_float2(__uint_as_float(a), __uint_as_float(b));
}
#define FMA2(acc, a, b) \
    asm("fma.rn.f32x2 %0, %1, %2, %0;" : "+l"(acc) : "l"(a), "l"(b))

// ---------------- K0: permutation (byte offsets *16) + BN zero --------------
__global__ void k0_prep(const int* __restrict__ neigh) {
    int j = blockIdx.x * 256 + threadIdx.x;
    if (j < JTOT) {
        int n = j & (NPTS - 1);
        int k = j >> 12;
        d_P[j] = (unsigned short)(neigh[n * KNB + k] * 16);
    }
    if (j < SDIM * C2V) { g_sum[j] = 0.f; g_sumsq[j] = 0.f; }
}

// ---------------- KT: scatter-transpose input -> Tflat ----------------------
// Tflat[bs][jt] = input[bs][n][k] where jt = k*4096 + n.  Read coalesced
// (memory order m = n*9+k), write 9-line scatter.
__global__ void __launch_bounds__(256) kt_transpose(const float* __restrict__ in)
{
    int g = blockIdx.x * 256 + threadIdx.x;          // global element id
    int bs = g / JTOT;
    int m  = g - bs * JTOT;
    float v = __ldg(in + g);
    int n = m / KNB;
    int k = m - n * KNB;
    g_T[(size_t)bs * JTOT + k * NPTS + n] = v;
}

// ---------------- K1: stage 1 (9-tap conv on Tflat, smem-staged) ------------
// Block handles 256 consecutive points of one bs. Needed window of Tflat is
// contiguous: [p0*9, p0*9+2304). Stage through smem; per-thread reads are
// stride-9 floats => all 32 banks distinct => conflict-free.
__global__ void __launch_bounds__(256) k1_stage1(
    const float* __restrict__ W1, const float* __restrict__ b1)
{
    __shared__ __align__(16) float sh_t[2304];
    __shared__ __align__(16) unsigned long long sw[KNB * 16];
    __shared__ unsigned long long sb[16];
    int t = threadIdx.x;
    if (t < KNB * 16) {
        int q = t >> 4, oh = t & 15;
        sw[t] = pack2(W1[(2 * oh) * KNB + q], W1[(2 * oh + 1) * KNB + q]);
    }
    if (t < 16) sb[t] = pack2(b1[2 * t], b1[2 * t + 1]);

    int blk = blockIdx.x;
    int bs  = blk >> 4;
    int p0  = (blk & 15) * 256;

    // stage window (2304 floats = 576 float4, 16B-aligned since p0*9*4 % 16 == 0)
    const float4* src = (const float4*)(g_T + (size_t)bs * JTOT + p0 * KNB);
    float4* dst4 = (float4*)sh_t;
    for (int i = t; i < 576; i += 256) dst4[i] = src[i];
    __syncthreads();

    unsigned long long acc[16];
#pragma unroll
    for (int oh = 0; oh < 16; oh++) acc[oh] = sb[oh];

    const float* row = sh_t + t * KNB;
#pragma unroll
    for (int q = 0; q < KNB; q++) {
        float v = row[q];
        unsigned long long v2 = pack2(v, v);
        const ulonglong2* w = (const ulonglong2*)(sw + q * 16);
#pragma unroll
        for (int oh2 = 0; oh2 < 8; oh2++) {
            ulonglong2 ww = w[oh2];
            FMA2(acc[2 * oh2],     v2, ww.x);
            FMA2(acc[2 * oh2 + 1], v2, ww.y);
        }
    }

    float4* hp = g_h4 + (size_t)bs * (8 * NPTS) + (p0 + t);
#pragma unroll
    for (int qb = 0; qb < 8; qb++) {
        float2 a = unpack2(acc[2 * qb]);
        float2 b = unpack2(acc[2 * qb + 1]);
        hp[qb * NPTS] = make_float4(fmaxf(a.x, 0.f), fmaxf(a.y, 0.f),
                                    fmaxf(b.x, 0.f), fmaxf(b.y, 0.f));
    }
}

// ---------------- K2: gather + GEMM (4 streams, zero-MOV FFMA2) + BN --------
// Block (bs, qb): channels 4qb..4qb+3 as float4 smem slice. Thread t handles
// p'_s = qb*512 + s*128 + t. The LDS.128 gather result is used DIRECTLY as
// two packed f32x2 multiplicands (ch0,ch1) and (ch2,ch3); accumulators are
// stream-paired; weights are pre-splatted in smem.
__global__ void __launch_bounds__(128) k2_stage2(
    const float* __restrict__ W2, const float* __restrict__ b2)
{
    extern __shared__ char smem[];
    float4* sh_h = (float4*)smem;                                     // 64 KB
    unsigned long long* sh_ws = (unsigned long long*)(smem + 65536);  // 36 KB
    float* red_s = (float*)(smem + 65536 + 36864);
    float* red_q = red_s + 64;

    int blk = blockIdx.x;
    int bs  = blk >> 3;
    int qb  = blk & 7;
    int t   = threadIdx.x;

    const float4* hsrc = g_h4 + ((size_t)bs * 8 + qb) * NPTS;
    for (int i = t; i < NPTS; i += 128) sh_h[i] = hsrc[i];
    // splat table: sh_ws[q*16 + o] = (W2[o][q], W2[o][q])
    for (int i = t; i < 288 * 16; i += 128) {
        int q = i >> 4, o = i & 15;
        float w = W2[o * 288 + q];
        sh_ws[i] = pack2(w, w);
    }
    __syncthreads();

    unsigned long long acc01[16], acc23[16];
#pragma unroll
    for (int o = 0; o < 16; o++) {
        float bb = __ldg(b2 + o);
        unsigned long long bp = pack2(bb, bb);
        acc01[o] = bp; acc23[o] = bp;
    }

    const char* hbase = (const char*)sh_h;
    const uint4* Pp = (const uint4*)(d_P) + t * 36;   // row t: 288 u16 offsets
#pragma unroll 2
    for (int q8 = 0; q8 < 36; q8++) {
        uint4 pv = Pp[q8];
        unsigned off[8] = { pv.x & 0xFFFFu, pv.x >> 16,
                            pv.y & 0xFFFFu, pv.y >> 16,
                            pv.z & 0xFFFFu, pv.z >> 16,
                            pv.w & 0xFFFFu, pv.w >> 16 };
#pragma unroll
        for (int j = 0; j < 8; j++) {
            ulonglong2 hv = *(const ulonglong2*)(hbase + off[j]); // (ch0,ch1),(ch2,ch3)
            const ulonglong2* ws = (const ulonglong2*)(sh_ws + (q8 * 8 + j) * 16);
#pragma unroll
            for (int o2 = 0; o2 < 8; o2++) {
                ulonglong2 wv = ws[o2];
                FMA2(acc01[2 * o2],     hv.x, wv.x);
                FMA2(acc01[2 * o2 + 1], hv.x, wv.y);
                FMA2(acc23[2 * o2],     hv.y, wv.x);
                FMA2(acc23[2 * o2 + 1], hv.y, wv.y);
            }
        }
    }

    // unpack, write y2, accumulate BN stats
    float* dst = g_y2 + (size_t)bs * (C2V * NPTS) + qb * 512 + t;
    float vsum[16], vsq[16];
#pragma unroll
    for (int o = 0; o < 16; o++) {
        float2 f01 = unpack2(acc01[o]);
        float2 f23 = unpack2(acc23[o]);
        dst[o * NPTS]       = f01.x;
        dst[o * NPTS + 128] = f01.y;
        dst[o * NPTS + 256] = f23.x;
        dst[o * NPTS + 384] = f23.y;
        vsum[o] = f01.x + f01.y + f23.x + f23.y;
        vsq[o]  = f01.x * f01.x + f01.y * f01.y + f23.x * f23.x + f23.y * f23.y;
    }

    int warp = t >> 5, lane = t & 31;
#pragma unroll
    for (int o = 0; o < 16; o++) {
        float v = vsum[o], sq = vsq[o];
#pragma unroll
        for (int off2 = 16; off2; off2 >>= 1) {
            v  += __shfl_down_sync(0xFFFFFFFFu, v,  off2);
            sq += __shfl_down_sync(0xFFFFFFFFu, sq, off2);
        }
        if (lane == 0) { red_s[warp * 16 + o] = v; red_q[warp * 16 + o] = sq; }
    }
    __syncthreads();
    if (t < 16) {
        float a = red_s[t] + red_s[16 + t] + red_s[32 + t] + red_s[48 + t];
        float q = red_q[t] + red_q[16 + t] + red_q[32 + t] + red_q[48 + t];
        int s = bs % SDIM;
        atomicAdd(&g_sum[s * C2V + t], a);
        atomicAdd(&g_sumsq[s * C2V + t], q);
    }
}

// ---------------- K2b: finalize BN scale/shift per (s, o) -------------------
__global__ void k2b_bnfinal(const float* __restrict__ gamma,
                            const float* __restrict__ beta)
{
    int i = threadIdx.x;
    if (i < SDIM * C2V) {
        const float cnt = 8.0f * (float)NPTS;   // B * N = 32768
        float mean = g_sum[i] / cnt;
        float var  = g_sumsq[i] / cnt - mean * mean;
        int o = i & 15;
        float A = gamma[o] * rsqrtf(var + BN_EPS);
        g_A[i] = A;
        g_B[i] = beta[o] - mean * A;
    }
}

// ---------------- K3: BN+relu, 4-stream gather, 144-dot, relu ---------------
__global__ void __launch_bounds__(256) k3_stage3(
    const float* __restrict__ W3, const float* __restrict__ b3,
    float* __restrict__ out)
{
    extern __shared__ char smem3[];
    float4* sh_v = (float4*)smem3;                                   // 64 KB
    unsigned long long* sw3p = (unsigned long long*)(smem3 + 65536); // 144*8

    int blk = blockIdx.x;
    int bs  = blk >> 2;
    int cb4 = blk & 3;
    int o0  = 4 * cb4;
    int t   = threadIdx.x;
    int s   = bs % SDIM;

    float A0 = g_A[s * C2V + o0],     B0 = g_B[s * C2V + o0];
    float A1 = g_A[s * C2V + o0 + 1], B1 = g_B[s * C2V + o0 + 1];
    float A2 = g_A[s * C2V + o0 + 2], B2 = g_B[s * C2V + o0 + 2];
    float A3 = g_A[s * C2V + o0 + 3], B3 = g_B[s * C2V + o0 + 3];

    const float4* s0 = (const float4*)(g_y2 + ((size_t)bs * C2V + o0) * NPTS);
    const float4* s1 = (const float4*)(g_y2 + ((size_t)bs * C2V + o0 + 1) * NPTS);
    const float4* s2 = (const float4*)(g_y2 + ((size_t)bs * C2V + o0 + 2) * NPTS);
    const float4* s3 = (const float4*)(g_y2 + ((size_t)bs * C2V + o0 + 3) * NPTS);
    for (int i = t; i < NPTS / 4; i += 256) {
        float4 a = s0[i], b = s1[i], c = s2[i], d = s3[i];
        sh_v[4 * i + 0] = make_float4(fmaxf(fmaf(a.x, A0, B0), 0.f), fmaxf(fmaf(b.x, A1, B1), 0.f),
                                      fmaxf(fmaf(c.x, A2, B2), 0.f), fmaxf(fmaf(d.x, A3, B3), 0.f));
        sh_v[4 * i + 1] = make_float4(fmaxf(fmaf(a.y, A0, B0), 0.f), fmaxf(fmaf(b.y, A1, B1), 0.f),
                                      fmaxf(fmaf(c.y, A2, B2), 0.f), fmaxf(fmaf(d.y, A3, B3), 0.f));
        sh_v[4 * i + 2] = make_float4(fmaxf(fmaf(a.z, A0, B0), 0.f), fmaxf(fmaf(b.z, A1, B1), 0.f),
                                      fmaxf(fmaf(c.z, A2, B2), 0.f), fmaxf(fmaf(d.z, A3, B3), 0.f));
        sh_v[4 * i + 3] = make_float4(fmaxf(fmaf(a.w, A0, B0), 0.f), fmaxf(fmaf(b.w, A1, B1), 0.f),
                                      fmaxf(fmaf(c.w, A2, B2), 0.f), fmaxf(fmaf(d.w, A3, B3), 0.f));
    }
    if (t < 144) { float w = W3[t]; sw3p[t] = pack2(w, w); }
    __syncthreads();

    float bv = __ldg(b3);
    unsigned long long acc01 = pack2(bv, bv);
    unsigned long long acc23 = pack2(bv, bv);
    const char* vbase = (const char*)sh_v;
    const uint4* Pp = (const uint4*)(d_P) + t * 18;
#pragma unroll 3
    for (int q8 = 0; q8 < 18; q8++) {
        uint4 pv = Pp[q8];
        unsigned off[8] = { pv.x & 0xFFFFu, pv.x >> 16,
                            pv.y & 0xFFFFu, pv.y >> 16,
                            pv.z & 0xFFFFu, pv.z >> 16,
                            pv.w & 0xFFFFu, pv.w >> 16 };
#pragma unroll
        for (int j = 0; j < 8; j++) {
            ulonglong2 vv = *(const ulonglong2*)(vbase + off[j]);
            unsigned long long ww = sw3p[q8 * 8 + j];
            FMA2(acc01, vv.x, ww);
            FMA2(acc23, vv.y, ww);
        }
    }
    float2 r01 = unpack2(acc01);
    float2 r23 = unpack2(acc23);
    float* op = out + (size_t)bs * NPTS + cb4 * 1024 + t;
    op[0]   = fmaxf(r01.x, 0.f);
    op[256] = fmaxf(r01.y, 0.f);
    op[512] = fmaxf(r23.x, 0.f);
    op[768] = fmaxf(r23.y, 0.f);
}

// ---------------- launch -----------------------------------------------------
extern "C" void kernel_launch(void* const* d_in, const int* in_sizes, int n_in,
                              void* d_out, int out_size)
{
    const float* input = (const float*)d_in[0];
    const int*   neigh = (const int*)  d_in[1];
    const float* W1    = (const float*)d_in[2];
    const float* b1    = (const float*)d_in[3];
    const float* W2    = (const float*)d_in[4];
    const float* b2    = (const float*)d_in[5];
    const float* gamma = (const float*)d_in[6];
    const float* beta  = (const float*)d_in[7];
    const float* W3    = (const float*)d_in[8];
    const float* b3    = (const float*)d_in[9];
    float* out = (float*)d_out;

    static int smem_set = 0;
    if (!smem_set) {
        cudaFuncSetAttribute(k2_stage2, cudaFuncAttributeMaxDynamicSharedMemorySize,
                             65536 + 36864 + 512);
        cudaFuncSetAttribute(k3_stage3, cudaFuncAttributeMaxDynamicSharedMemorySize,
                             65536 + 144 * 8);
        smem_set = 1;
    }

    k0_prep<<<144, 256>>>(neigh);
    kt_transpose<<<(BS_TOT * JTOT) / 256, 256>>>(input);
    k1_stage1<<<BS_TOT * 16, 256>>>(W1, b1);
    k2_stage2<<<BS_TOT * 8, 128, 65536 + 36864 + 512>>>(W2, b2);
    k2b_bnfinal<<<1, 384>>>(gamma, beta);
    k3_stage3<<<BS_TOT * 4, 256, 65536 + 144 * 8>>>(W3, b3, out);
}

// round 6
// speedup vs baseline: 1.0006x; 1.0006x over previous
#include <cuda_runtime.h>
#include <cstdint>
#include <cstddef>

// Problem constants (B=8, S=24, N=4096, K=9, C1=32, C2=16)
#define BS_TOT 192
#define SDIM   24
#define NPTS   4096
#define KNB    9
#define C1V    32
#define C2V    16
#define JTOT   36864   // KNB * NPTS
#define BN_EPS 1e-5f

// ---------------- device scratch (static globals: allocation-free) ----------
__device__ __align__(16) unsigned short d_P[JTOT];  // gather byte-offsets (*16)
__device__ float g_sum[SDIM * C2V];
__device__ float g_sumsq[SDIM * C2V];
__device__ float g_A[SDIM * C2V];
__device__ float g_B[SDIM * C2V];
__device__ float g_T[(size_t)BS_TOT * JTOT];          // transposed input (27 MB)
// h in 4-channel-interleaved layout: g_h4[(bs*8 + qb)*NPTS + p]
__device__ float4 g_h4[(size_t)BS_TOT * 8 * NPTS];    // 96 MB
__device__ float  g_y2[(size_t)BS_TOT * C2V * NPTS];  // stage-2 out (48 MB)

// ---------------- packed f32x2 helpers (sm_103a FFMA2 path) ----------------
__device__ __forceinline__ unsigned long long pack2(float x, float y) {
    unsigned long long r;
    asm("mov.b64 %0, {%1, %2};" : "=l"(r)
        : "r"(__float_as_uint(x)), "r"(__float_as_uint(y)));
    return r;
}
__device__ __forceinline__ float2 unpack2(unsigned long long v) {
    unsigned int a, b;
    asm("mov.b64 {%0, %1}, %2;" : "=r"(a), "=r"(b) : "l"(v));
    return make_float2(__uint_as_float(a), __uint_as_float(b));
}
#define FMA2(acc, a, b) \
    asm("fma.rn.f32x2 %0, %1, %2, %0;" : "+l"(acc) : "l"(a), "l"(b))

// ---------------- K0: permutation (byte offsets *16) + BN zero --------------
__global__ void k0_prep(const int* __restrict__ neigh) {
    int j = blockIdx.x * 256 + threadIdx.x;
    if (j < JTOT) {
        int n = j & (NPTS - 1);
        int k = j >> 12;
        d_P[j] = (unsigned short)(neigh[n * KNB + k] * 16);
    }
    if (j < SDIM * C2V) { g_sum[j] = 0.f; g_sumsq[j] = 0.f; }
}

// ---------------- KT: scatter-transpose input -> Tflat ----------------------
__global__ void __launch_bounds__(256) kt_transpose(const float* __restrict__ in)
{
    int g = blockIdx.x * 256 + threadIdx.x;
    int bs = g / JTOT;
    int m  = g - bs * JTOT;
    float v = __ldg(in + g);
    int n = m / KNB;
    int k = m - n * KNB;
    g_T[(size_t)bs * JTOT + k * NPTS + n] = v;
}

// ---------------- K1: stage 1 (9-tap conv on Tflat, smem-staged) ------------
__global__ void __launch_bounds__(256) k1_stage1(
    const float* __restrict__ W1, const float* __restrict__ b1)
{
    __shared__ __align__(16) float sh_t[2304];
    __shared__ __align__(16) unsigned long long sw[KNB * 16];
    __shared__ unsigned long long sb[16];
    int t = threadIdx.x;
    if (t < KNB * 16) {
        int q = t >> 4, oh = t & 15;
        sw[t] = pack2(W1[(2 * oh) * KNB + q], W1[(2 * oh + 1) * KNB + q]);
    }
    if (t < 16) sb[t] = pack2(b1[2 * t], b1[2 * t + 1]);

    int blk = blockIdx.x;
    int bs  = blk >> 4;
    int p0  = (blk & 15) * 256;

    const float4* src = (const float4*)(g_T + (size_t)bs * JTOT + p0 * KNB);
    float4* dst4 = (float4*)sh_t;
    for (int i = t; i < 576; i += 256) dst4[i] = src[i];
    __syncthreads();

    unsigned long long acc[16];
#pragma unroll
    for (int oh = 0; oh < 16; oh++) acc[oh] = sb[oh];

    const float* row = sh_t + t * KNB;
#pragma unroll
    for (int q = 0; q < KNB; q++) {
        float v = row[q];
        unsigned long long v2 = pack2(v, v);
        const ulonglong2* w = (const ulonglong2*)(sw + q * 16);
#pragma unroll
        for (int oh2 = 0; oh2 < 8; oh2++) {
            ulonglong2 ww = w[oh2];
            FMA2(acc[2 * oh2],     v2, ww.x);
            FMA2(acc[2 * oh2 + 1], v2, ww.y);
        }
    }

    float4* hp = g_h4 + (size_t)bs * (8 * NPTS) + (p0 + t);
#pragma unroll
    for (int qb = 0; qb < 8; qb++) {
        float2 a = unpack2(acc[2 * qb]);
        float2 b = unpack2(acc[2 * qb + 1]);
        hp[qb * NPTS] = make_float4(fmaxf(a.x, 0.f), fmaxf(a.y, 0.f),
                                    fmaxf(b.x, 0.f), fmaxf(b.y, 0.f));
    }
}

// ---------------- K2: gather + GEMM, 8 p'-streams/thread + BN stats ---------
// Block (bs, qb4): TWO 4-channel slices (channels 8qb4..8qb4+7) in smem.
// Thread t handles p'_s = qb4*1024 + s*128 + t (s=0..7); all eight share
// gather row t. Per j: 2 LDS.128 gathers + 8 splat-pair broadcasts feed
// 64 FFMA2 -> FMA-pipe-bound, crossbar ~20cyc < FMA 32 SM-cyc.
__global__ void __launch_bounds__(128, 1) k2_stage2(
    const float* __restrict__ W2, const float* __restrict__ b2)
{
    extern __shared__ char smem[];
    float4* sh_hA = (float4*)smem;                                     // 64 KB
    float4* sh_hB = (float4*)(smem + 65536);                           // 64 KB
    unsigned long long* sh_ws = (unsigned long long*)(smem + 131072);  // 36 KB
    float* red_s = (float*)(smem + 131072 + 36864);
    float* red_q = red_s + 64;

    int blk = blockIdx.x;
    int bs  = blk >> 2;
    int qb4 = blk & 3;
    int t   = threadIdx.x;

    const float4* hsrcA = g_h4 + ((size_t)bs * 8 + 2 * qb4) * NPTS;
    const float4* hsrcB = g_h4 + ((size_t)bs * 8 + 2 * qb4 + 1) * NPTS;
    for (int i = t; i < NPTS; i += 128) { sh_hA[i] = hsrcA[i]; sh_hB[i] = hsrcB[i]; }
    // splat table: sh_ws[q*16 + o] = (W2[o][q], W2[o][q])
    for (int i = t; i < 288 * 16; i += 128) {
        int q = i >> 4, o = i & 15;
        float w = W2[o * 288 + q];
        sh_ws[i] = pack2(w, w);
    }
    __syncthreads();

    // acc[p][o]: stream pair (2p, 2p+1), output o
    unsigned long long a0[16], a1[16], a2[16], a3[16];
#pragma unroll
    for (int o = 0; o < 16; o++) {
        float bb = __ldg(b2 + o);
        unsigned long long bp = pack2(bb, bb);
        a0[o] = bp; a1[o] = bp; a2[o] = bp; a3[o] = bp;
    }

    const char* hbA = (const char*)sh_hA;
    const char* hbB = (const char*)sh_hB;
    const uint4* Pp = (const uint4*)(d_P) + t * 36;   // row t: 288 u16 offsets
#pragma unroll 1
    for (int q8 = 0; q8 < 36; q8++) {
        uint4 pv = Pp[q8];
        unsigned off[8] = { pv.x & 0xFFFFu, pv.x >> 16,
                            pv.y & 0xFFFFu, pv.y >> 16,
                            pv.z & 0xFFFFu, pv.z >> 16,
                            pv.w & 0xFFFFu, pv.w >> 16 };
#pragma unroll
        for (int j = 0; j < 8; j++) {
            ulonglong2 hA = *(const ulonglong2*)(hbA + off[j]); // (ch0,ch1),(ch2,ch3)
            ulonglong2 hB = *(const ulonglong2*)(hbB + off[j]); // (ch4,ch5),(ch6,ch7)
            const ulonglong2* ws = (const ulonglong2*)(sh_ws + (q8 * 8 + j) * 16);
#pragma unroll
            for (int o2 = 0; o2 < 8; o2++) {
                ulonglong2 wv = ws[o2];   // splats for outputs 2o2, 2o2+1
                FMA2(a0[2 * o2],     hA.x, wv.x);
                FMA2(a0[2 * o2 + 1], hA.x, wv.y);
                FMA2(a1[2 * o2],     hA.y, wv.x);
                FMA2(a1[2 * o2 + 1], hA.y, wv.y);
                FMA2(a2[2 * o2],     hB.x, wv.x);
                FMA2(a2[2 * o2 + 1], hB.x, wv.y);
                FMA2(a3[2 * o2],     hB.y, wv.x);
                FMA2(a3[2 * o2 + 1], hB.y, wv.y);
            }
        }
    }

    // unpack, write y2 (coalesced per warp), accumulate BN stats
    float* dst = g_y2 + (size_t)bs * (C2V * NPTS) + qb4 * 1024 + t;
    float vsum[16], vsq[16];
#pragma unroll
    for (int o = 0; o < 16; o++) {
        float2 f0 = unpack2(a0[o]);
        float2 f1 = unpack2(a1[o]);
        float2 f2 = unpack2(a2[o]);
        float2 f3 = unpack2(a3[o]);
        dst[o * NPTS + 0 * 128] = f0.x;
        dst[o * NPTS + 1 * 128] = f0.y;
        dst[o * NPTS + 2 * 128] = f1.x;
        dst[o * NPTS + 3 * 128] = f1.y;
        dst[o * NPTS + 4 * 128] = f2.x;
        dst[o * NPTS + 5 * 128] = f2.y;
        dst[o * NPTS + 6 * 128] = f3.x;
        dst[o * NPTS + 7 * 128] = f3.y;
        vsum[o] = (f0.x + f0.y) + (f1.x + f1.y) + (f2.x + f2.y) + (f3.x + f3.y);
        vsq[o]  = (f0.x * f0.x + f0.y * f0.y) + (f1.x * f1.x + f1.y * f1.y)
                + (f2.x * f2.x + f2.y * f2.y) + (f3.x * f3.x + f3.y * f3.y);
    }

    int warp = t >> 5, lane = t & 31;
#pragma unroll
    for (int o = 0; o < 16; o++) {
        float v = vsum[o], sq = vsq[o];
#pragma unroll
        for (int off2 = 16; off2; off2 >>= 1) {
            v  += __shfl_down_sync(0xFFFFFFFFu, v,  off2);
            sq += __shfl_down_sync(0xFFFFFFFFu, sq, off2);
        }
        if (lane == 0) { red_s[warp * 16 + o] = v; red_q[warp * 16 + o] = sq; }
    }
    __syncthreads();
    if (t < 16) {
        float a = red_s[t] + red_s[16 + t] + red_s[32 + t] + red_s[48 + t];
        float q = red_q[t] + red_q[16 + t] + red_q[32 + t] + red_q[48 + t];
        int s = bs % SDIM;
        atomicAdd(&g_sum[s * C2V + t], a);
        atomicAdd(&g_sumsq[s * C2V + t], q);
    }
}

// ---------------- K2b: finalize BN scale/shift per (s, o) -------------------
__global__ void k2b_bnfinal(const float* __restrict__ gamma,
                            const float* __restrict__ beta)
{
    int i = threadIdx.x;
    if (i < SDIM * C2V) {
        const float cnt = 8.0f * (float)NPTS;   // B * N = 32768
        float mean = g_sum[i] / cnt;
        float var  = g_sumsq[i] / cnt - mean * mean;
        int o = i & 15;
        float A = gamma[o] * rsqrtf(var + BN_EPS);
        g_A[i] = A;
        g_B[i] = beta[o] - mean * A;
    }
}

// ---------------- K3: BN+relu, 4-stream gather, 144-dot, relu ---------------
__global__ void __launch_bounds__(256) k3_stage3(
    const float* __restrict__ W3, const float* __restrict__ b3,
    float* __restrict__ out)
{
    extern __shared__ char smem3[];
    float4* sh_v = (float4*)smem3;                                   // 64 KB
    unsigned long long* sw3p = (unsigned long long*)(smem3 + 65536); // 144*8

    int blk = blockIdx.x;
    int bs  = blk >> 2;
    int cb4 = blk & 3;
    int o0  = 4 * cb4;
    int t   = threadIdx.x;
    int s   = bs % SDIM;

    float A0 = g_A[s * C2V + o0],     B0 = g_B[s * C2V + o0];
    float A1 = g_A[s * C2V + o0 + 1], B1 = g_B[s * C2V + o0 + 1];
    float A2 = g_A[s * C2V + o0 + 2], B2 = g_B[s * C2V + o0 + 2];
    float A3 = g_A[s * C2V + o0 + 3], B3 = g_B[s * C2V + o0 + 3];

    const float4* s0 = (const float4*)(g_y2 + ((size_t)bs * C2V + o0) * NPTS);
    const float4* s1 = (const float4*)(g_y2 + ((size_t)bs * C2V + o0 + 1) * NPTS);
    const float4* s2 = (const float4*)(g_y2 + ((size_t)bs * C2V + o0 + 2) * NPTS);
    const float4* s3 = (const float4*)(g_y2 + ((size_t)bs * C2V + o0 + 3) * NPTS);
    for (int i = t; i < NPTS / 4; i += 256) {
        float4 a = s0[i], b = s1[i], c = s2[i], d = s3[i];
        sh_v[4 * i + 0] = make_float4(fmaxf(fmaf(a.x, A0, B0), 0.f), fmaxf(fmaf(b.x, A1, B1), 0.f),
                                      fmaxf(fmaf(c.x, A2, B2), 0.f), fmaxf(fmaf(d.x, A3, B3), 0.f));
        sh_v[4 * i + 1] = make_float4(fmaxf(fmaf(a.y, A0, B0), 0.f), fmaxf(fmaf(b.y, A1, B1), 0.f),
                                      fmaxf(fmaf(c.y, A2, B2), 0.f), fmaxf(fmaf(d.y, A3, B3), 0.f));
        sh_v[4 * i + 2] = make_float4(fmaxf(fmaf(a.z, A0, B0), 0.f), fmaxf(fmaf(b.z, A1, B1), 0.f),
                                      fmaxf(fmaf(c.z, A2, B2), 0.f), fmaxf(fmaf(d.z, A3, B3), 0.f));
        sh_v[4 * i + 3] = make_float4(fmaxf(fmaf(a.w, A0, B0), 0.f), fmaxf(fmaf(b.w, A1, B1), 0.f),
                                      fmaxf(fmaf(c.w, A2, B2), 0.f), fmaxf(fmaf(d.w, A3, B3), 0.f));
    }
    if (t < 144) { float w = W3[t]; sw3p[t] = pack2(w, w); }
    __syncthreads();

    float bv = __ldg(b3);
    unsigned long long acc01 = pack2(bv, bv);
    unsigned long long acc23 = pack2(bv, bv);
    const char* vbase = (const char*)sh_v;
    const uint4* Pp = (const uint4*)(d_P) + t * 18;
#pragma unroll 3
    for (int q8 = 0; q8 < 18; q8++) {
        uint4 pv = Pp[q8];
        unsigned off[8] = { pv.x & 0xFFFFu, pv.x >> 16,
                            pv.y & 0xFFFFu, pv.y >> 16,
                            pv.z & 0xFFFFu, pv.z >> 16,
                            pv.w & 0xFFFFu, pv.w >> 16 };
#pragma unroll
        for (int j = 0; j < 8; j++) {
            ulonglong2 vv = *(const ulonglong2*)(vbase + off[j]);
            unsigned long long ww = sw3p[q8 * 8 + j];
            FMA2(acc01, vv.x, ww);
            FMA2(acc23, vv.y, ww);
        }
    }
    float2 r01 = unpack2(acc01);
    float2 r23 = unpack2(acc23);
    float* op = out + (size_t)bs * NPTS + cb4 * 1024 + t;
    op[0]   = fmaxf(r01.x, 0.f);
    op[256] = fmaxf(r01.y, 0.f);
    op[512] = fmaxf(r23.x, 0.f);
    op[768] = fmaxf(r23.y, 0.f);
}

// ---------------- launch -----------------------------------------------------
extern "C" void kernel_launch(void* const* d_in, const int* in_sizes, int n_in,
                              void* d_out, int out_size)
{
    const float* input = (const float*)d_in[0];
    const int*   neigh = (const int*)  d_in[1];
    const float* W1    = (const float*)d_in[2];
    const float* b1    = (const float*)d_in[3];
    const float* W2    = (const float*)d_in[4];
    const float* b2    = (const float*)d_in[5];
    const float* gamma = (const float*)d_in[6];
    const float* beta  = (const float*)d_in[7];
    const float* W3    = (const float*)d_in[8];
    const float* b3    = (const float*)d_in[9];
    float* out = (float*)d_out;

    static int smem_set = 0;
    if (!smem_set) {
        cudaFuncSetAttribute(k2_stage2, cudaFuncAttributeMaxDynamicSharedMemorySize,
                             131072 + 36864 + 512);
        cudaFuncSetAttribute(k3_stage3, cudaFuncAttributeMaxDynamicSharedMemorySize,
                             65536 + 144 * 8);
        smem_set = 1;
    }

    k0_prep<<<144, 256>>>(neigh);
    kt_transpose<<<(BS_TOT * JTOT) / 256, 256>>>(input);
    k1_stage1<<<BS_TOT * 16, 256>>>(W1, b1);
    k2_stage2<<<BS_TOT * 4, 128, 131072 + 36864 + 512>>>(W2, b2);
    k2b_bnfinal<<<1, 384>>>(gamma, beta);
    k3_stage3<<<BS_TOT * 4, 256, 65536 + 144 * 8>>>(W3, b3, out);
}